// round 14
// baseline (speedup 1.0000x reference)
#include <cuda_runtime.h>

#define NDIM 8192
#define MDIM 4096
#define CDIM 1024
#define ADIM 256
#define XDIM 1280
#define NBLK 444                  // 3 per SM x 148
#define ROWS_PER 19               // ceil(8192/444)
#define NWARPS (NBLK * 16)        // 7104
#define NPIECE (2 * 6 * CDIM)     // 12288 half-rows

// Scratch (static device globals — no runtime allocation)
__device__ float g_dots_h[NPIECE];        // half-row GRU dot partials
__device__ float g_pr[NDIM];              // unnormalized pow(read)
__device__ float g_pw[NDIM];              // unnormalized pow(write)
__device__ float g_spr[NBLK];             // per-block pow sums
__device__ float g_spw[NBLK];
__device__ float g_partial[NBLK * MDIM];  // gemv partials
__device__ unsigned g_bar1, g_bar2;

// Ticket barrier: never resets, correct across unlimited graph replays.
__device__ __forceinline__ void grid_sync(unsigned* bar) {
    __syncthreads();
    if (threadIdx.x == 0) {
        __threadfence();
        unsigned t = atomicAdd(bar, 1u);
        unsigned target = (t / NBLK + 1u) * NBLK;
        while (*(volatile unsigned*)bar < target) __nanosleep(32);
    }
    __syncthreads();
    __threadfence();
}

__global__ void __launch_bounds__(512, 3) fused_kernel(
    const float* __restrict__ action, const float* __restrict__ hid,
    const float* __restrict__ prev_r, const float* __restrict__ prev_w,
    const float* __restrict__ hprev, const float* __restrict__ mem,
    const float* __restrict__ W_ih, const float* __restrict__ W_hh,
    const float* __restrict__ b_ih, const float* __restrict__ b_hh,
    const float* __restrict__ W_gamma, const float* __restrict__ b_gamma,
    const float* __restrict__ W_gate, const float* __restrict__ b_gate,
    float* __restrict__ out)
{
    const int tid = threadIdx.x;
    const int b   = blockIdx.x;

    __shared__ float4 smt[64][8];             // 4 KB column-reduce tree
    __shared__ float  s_a[512], s_b[512];     // 4 KB reduce trees
    __shared__ float  w_s[32];
    __shared__ float  sh_gate, sh_gamma, sh_invSr, sh_invSw;

    // ============ Phase 1: GRU dot products over half-rows =================
    // 12288 pieces (row = p>>1, half = p&1), 7104 warps -> <=2 pieces/warp.
    {
        const int lane = tid & 31;
        const int wg   = b * 16 + (tid >> 5);
        const float4* a4 = (const float4*)action;   // 64 groups
        const float4* x4 = (const float4*)hid;      // 256 groups
        const float4* h4 = (const float4*)hprev;    // 256 groups
        for (int p = wg; p < NPIECE; p += NWARPS) {
            int r  = p >> 1;
            int hf = p & 1;
            float s = 0.f;
            if (r < 3 * CDIM) {
                const float4* row = (const float4*)(W_ih + (size_t)r * XDIM);
                int base = hf * 160 + lane;
#pragma unroll
                for (int k = 0; k < 5; k++) {
                    int k4 = base + k * 32;
                    float4 rv = __ldcs(&row[k4]);
                    float4 xv = (k4 < ADIM / 4) ? a4[k4] : x4[k4 - ADIM / 4];
                    s += rv.x * xv.x + rv.y * xv.y + rv.z * xv.z + rv.w * xv.w;
                }
            } else {
                const float4* row = (const float4*)(W_hh + (size_t)(r - 3 * CDIM) * CDIM);
                int base = hf * 128 + lane;
#pragma unroll
                for (int k = 0; k < 4; k++) {
                    int k4 = base + k * 32;
                    float4 rv = __ldcs(&row[k4]);
                    float4 xv = h4[k4];
                    s += rv.x * xv.x + rv.y * xv.y + rv.z * xv.z + rv.w * xv.w;
                }
            }
#pragma unroll
            for (int off = 16; off > 0; off >>= 1)
                s += __shfl_down_sync(0xffffffffu, s, off);
            if (lane == 0) g_dots_h[p] = s;
        }
    }
    grid_sync(&g_bar1);

    // == Phase 2: every block computes all h + gate/gamma (bit-identical) ===
    {
        float pa = 0.f, pb = 0.f;
#pragma unroll
        for (int j = 0; j < 2; j++) {
            int c = tid + j * 512;
            float d0 = g_dots_h[2 * c]                  + g_dots_h[2 * c + 1];
            float d1 = g_dots_h[2 * (CDIM + c)]         + g_dots_h[2 * (CDIM + c) + 1];
            float d2 = g_dots_h[2 * (2 * CDIM + c)]     + g_dots_h[2 * (2 * CDIM + c) + 1];
            float d3 = g_dots_h[2 * (3 * CDIM + c)]     + g_dots_h[2 * (3 * CDIM + c) + 1];
            float d4 = g_dots_h[2 * (4 * CDIM + c)]     + g_dots_h[2 * (4 * CDIM + c) + 1];
            float d5 = g_dots_h[2 * (5 * CDIM + c)]     + g_dots_h[2 * (5 * CDIM + c) + 1];
            float hp = hprev[c];
            float r = 1.f / (1.f + expf(-(d0 + b_ih[c] + d3 + b_hh[c])));
            float z = 1.f / (1.f + expf(-(d1 + b_ih[CDIM + c] + d4 + b_hh[CDIM + c])));
            float n = tanhf(d2 + b_ih[2 * CDIM + c] + r * (d5 + b_hh[2 * CDIM + c]));
            float h = (1.f - z) * n + z * hp;
            if (b == 0) out[MDIM + 2 * NDIM + c] = h;   // new_controller_hidden
            pa += W_gate[c] * h;
            pb += W_gamma[c] * h;
        }
        s_a[tid] = pa;
        s_b[tid] = pb;
        __syncthreads();
        for (int off = 256; off > 0; off >>= 1) {
            if (tid < off) { s_a[tid] += s_a[tid + off]; s_b[tid] += s_b[tid + off]; }
            __syncthreads();
        }
        if (tid == 0) {
            sh_gate = 1.f / (1.f + expf(-(s_a[0] + b_gate[0])));
            float x = s_b[0] + b_gamma[0];
            sh_gamma = (x > 20.f) ? x : log1pf(expf(x));   // softplus
        }
        __syncthreads();
    }

    // ======== Phase 3: pow weights + streaming GEMV over own rows ==========
    const int r0 = b * ROWS_PER;
    int nrows = NDIM - r0;
    if (nrows > ROWS_PER) nrows = ROWS_PER;
    if (nrows < 0) nrows = 0;

    {
        float gate = sh_gate, gamma = sh_gamma;
        if (tid < nrows) {
            int r = r0 + tid;
            float vr = gate + (1.f - gate) * prev_r[r];
            float vw = gate + (1.f - gate) * prev_w[r];
            float pr = powf(vr, gamma);
            float pw = powf(vw, gamma);
            g_pr[r] = pr; g_pw[r] = pw;
            w_s[tid] = pr;              // unnormalized weights drive the gemv
            s_a[tid] = pr; s_b[tid] = pw;
        }
        __syncthreads();
        if (tid == 0) {
            float sa = 0.f, sb = 0.f;
            for (int j = 0; j < nrows; j++) { sa += s_a[j]; sb += s_b[j]; }
            g_spr[b] = sa; g_spw[b] = sb;
        }

        // Each thread owns f4 groups tid and tid+512; unroll 2 rows.
        const float4* m4 = (const float4*)mem + (size_t)r0 * (MDIM / 4) + tid;
        float4 accA = make_float4(0.f, 0.f, 0.f, 0.f);   // cols group tid
        float4 accB = make_float4(0.f, 0.f, 0.f, 0.f);   // cols group tid+512
        int i = 0;
        for (; i + 2 <= nrows; i += 2) {
            float w0 = w_s[i], w1 = w_s[i + 1];
            const float4* p0 = m4 + (size_t)i * (MDIM / 4);
            const float4* p1 = p0 + (MDIM / 4);
            float4 vA0 = __ldcs(p0);
            float4 vB0 = __ldcs(p0 + 512);
            float4 vA1 = __ldcs(p1);
            float4 vB1 = __ldcs(p1 + 512);
            accA.x += w0 * vA0.x; accA.y += w0 * vA0.y;
            accA.z += w0 * vA0.z; accA.w += w0 * vA0.w;
            accB.x += w0 * vB0.x; accB.y += w0 * vB0.y;
            accB.z += w0 * vB0.z; accB.w += w0 * vB0.w;
            accA.x += w1 * vA1.x; accA.y += w1 * vA1.y;
            accA.z += w1 * vA1.z; accA.w += w1 * vA1.w;
            accB.x += w1 * vB1.x; accB.y += w1 * vB1.y;
            accB.z += w1 * vB1.z; accB.w += w1 * vB1.w;
        }
        if (i < nrows) {
            float w0 = w_s[i];
            const float4* p0 = m4 + (size_t)i * (MDIM / 4);
            float4 vA0 = __ldcs(p0);
            float4 vB0 = __ldcs(p0 + 512);
            accA.x += w0 * vA0.x; accA.y += w0 * vA0.y;
            accA.z += w0 * vA0.z; accA.w += w0 * vA0.w;
            accB.x += w0 * vB0.x; accB.y += w0 * vB0.y;
            accB.z += w0 * vB0.z; accB.w += w0 * vB0.w;
        }
        ((float4*)g_partial)[(size_t)b * (MDIM / 4) + tid]       = accA;
        ((float4*)g_partial)[(size_t)b * (MDIM / 4) + tid + 512] = accB;
    }
    grid_sync(&g_bar2);

    // ================= Phase 4: normalize + column reduce ==================
    {
        // global pow sums (fixed-order tree over 512 slots, NBLK=444 entries)
        s_a[tid] = (tid < NBLK) ? g_spr[tid] : 0.f;
        s_b[tid] = (tid < NBLK) ? g_spw[tid] : 0.f;
        __syncthreads();
        for (int off = 256; off > 0; off >>= 1) {
            if (tid < off) { s_a[tid] += s_a[tid + off]; s_b[tid] += s_b[tid + off]; }
            __syncthreads();
        }
        if (tid == 0) { sh_invSr = 1.f / s_a[0]; sh_invSw = 1.f / s_b[0]; }
        __syncthreads();
        float invSr = sh_invSr, invSw = sh_invSw;

        if (tid < nrows) {
            int r = r0 + tid;
            out[MDIM + r]        = g_pr[r] * invSr;  // read_weight
            out[MDIM + NDIM + r] = g_pw[r] * invSw;  // write_weight
        }

        // read_vector: blocks 0..127 each own 8 float4 column groups
        if (b < 128) {
            int cl    = tid & 7;
            int slice = tid >> 3;                    // 0..63
            int g4    = b * 8 + cl;
            const float4* p4 = (const float4*)g_partial + g4;
            float4 acc = make_float4(0.f, 0.f, 0.f, 0.f);
            for (int r = slice; r < NBLK; r += 64) {
                float4 v = p4[(size_t)r * (MDIM / 4)];
                acc.x += v.x; acc.y += v.y; acc.z += v.z; acc.w += v.w;
            }
            smt[slice][cl] = acc;
            __syncthreads();
            for (int off = 32; off > 0; off >>= 1) {
                if (slice < off) {
                    float4 a = smt[slice][cl];
                    float4 c = smt[slice + off][cl];
                    a.x += c.x; a.y += c.y; a.z += c.z; a.w += c.w;
                    smt[slice][cl] = a;
                }
                __syncthreads();
            }
            if (slice == 0) {
                float4 a = smt[0][cl];
                a.x *= invSr; a.y *= invSr; a.z *= invSr; a.w *= invSr;
                ((float4*)out)[g4] = a;              // read_vector
            }
        }
    }
}

extern "C" void kernel_launch(void* const* d_in, const int* in_sizes, int n_in,
                              void* d_out, int out_size)
{
    const float* action  = (const float*)d_in[0];   // (1,256)
    const float* hid     = (const float*)d_in[1];   // (1,1,1024)
    const float* prev_r  = (const float*)d_in[2];   // (8192,1)
    const float* prev_w  = (const float*)d_in[3];   // (8192,1)
    const float* hprev   = (const float*)d_in[4];   // (1,1,1024)
    const float* memory  = (const float*)d_in[5];   // (8192,4096)
    const float* W_ih    = (const float*)d_in[6];   // (3072,1280)
    const float* W_hh    = (const float*)d_in[7];   // (3072,1024)
    const float* b_ih    = (const float*)d_in[8];
    const float* b_hh    = (const float*)d_in[9];
    // d_in[10..19]: dead code (cosine-sim == 1, circ-conv scalar cancels in
    // sharpen, memory write discarded)
    const float* W_gamma = (const float*)d_in[20];
    const float* b_gamma = (const float*)d_in[21];
    const float* W_gate  = (const float*)d_in[22];
    const float* b_gate  = (const float*)d_in[23];

    float* out = (float*)d_out;
    // Layout: [0:4096) read_vector | [4096:12288) read_weight |
    //         [12288:20480) write_weight | [20480:21504) new_controller_hidden

    fused_kernel<<<NBLK, 512>>>(action, hid, prev_r, prev_w, hprev, memory,
                                W_ih, W_hh, b_ih, b_hh,
                                W_gamma, b_gamma, W_gate, b_gate, out);
}

// round 15
// speedup vs baseline: 1.0993x; 1.0993x over previous
#include <cuda_runtime.h>

#define NDIM 8192
#define MDIM 4096
#define CDIM 1024
#define ADIM 256
#define XDIM 1280
#define NBLK 148
#define ROWS_PER 56
#define NWARPS (NBLK * 32)        // 4736
#define NPIECE (2 * 6 * CDIM)     // 12288 half-rows

// Scratch (static device globals — no runtime allocation)
__device__ float g_dots_h[NPIECE];        // half-row GRU dot partials
__device__ float g_pr[NDIM];              // unnormalized pow(read)
__device__ float g_pw[NDIM];              // unnormalized pow(write)
__device__ float g_spr[NBLK];             // per-block pow sums
__device__ float g_spw[NBLK];
__device__ float g_partial[NBLK * MDIM];  // gemv partials
__device__ unsigned g_bar1, g_bar2;

// Ticket barrier: never resets, correct across unlimited graph replays.
__device__ __forceinline__ void grid_sync(unsigned* bar) {
    __syncthreads();
    if (threadIdx.x == 0) {
        __threadfence();
        unsigned t = atomicAdd(bar, 1u);
        unsigned target = (t / NBLK + 1u) * NBLK;
        while (*(volatile unsigned*)bar < target) __nanosleep(32);
    }
    __syncthreads();
    __threadfence();
}

// --- phase-1 piece processors (half-rows) ------------------------------
// ih piece p in [0,6144): row = p>>1 of W_ih, half = p&1 (160 f4, 5/lane)
__device__ __forceinline__ void do_ih_piece(
    int p, int lane, const float4* __restrict__ W_ih4,
    const float4* __restrict__ a4, const float4* __restrict__ x4)
{
    int r  = p >> 1;
    int hf = p & 1;
    const float4* row = W_ih4 + (size_t)r * (XDIM / 4);
    int base = hf * 160 + lane;
    float s = 0.f;
#pragma unroll
    for (int k = 0; k < 5; k++) {
        int k4 = base + k * 32;
        float4 rv = __ldcs(&row[k4]);
        float4 xv = (k4 < ADIM / 4) ? a4[k4] : x4[k4 - ADIM / 4];
        s += rv.x * xv.x + rv.y * xv.y + rv.z * xv.z + rv.w * xv.w;
    }
#pragma unroll
    for (int off = 16; off > 0; off >>= 1)
        s += __shfl_down_sync(0xffffffffu, s, off);
    if (lane == 0) g_dots_h[p] = s;
}

// hh piece p in [0,6144): row = p>>1 of W_hh, half = p&1 (128 f4, 4/lane)
__device__ __forceinline__ void do_hh_piece(
    int p, int lane, const float4* __restrict__ W_hh4,
    const float4* __restrict__ h4)
{
    int r  = p >> 1;
    int hf = p & 1;
    const float4* row = W_hh4 + (size_t)r * (CDIM / 4);
    int base = hf * 128 + lane;
    float s = 0.f;
#pragma unroll
    for (int k = 0; k < 4; k++) {
        int k4 = base + k * 32;
        float4 rv = __ldcs(&row[k4]);
        float4 xv = h4[k4];
        s += rv.x * xv.x + rv.y * xv.y + rv.z * xv.z + rv.w * xv.w;
    }
#pragma unroll
    for (int off = 16; off > 0; off >>= 1)
        s += __shfl_down_sync(0xffffffffu, s, off);
    if (lane == 0) g_dots_h[6144 + p] = s;
}

__global__ void __launch_bounds__(1024, 1) fused_kernel(
    const float* __restrict__ action, const float* __restrict__ hid,
    const float* __restrict__ prev_r, const float* __restrict__ prev_w,
    const float* __restrict__ hprev, const float* __restrict__ mem,
    const float* __restrict__ W_ih, const float* __restrict__ W_hh,
    const float* __restrict__ b_ih, const float* __restrict__ b_hh,
    const float* __restrict__ W_gamma, const float* __restrict__ b_gamma,
    const float* __restrict__ W_gate, const float* __restrict__ b_gate,
    float* __restrict__ out)
{
    const int tid = threadIdx.x;
    const int b   = blockIdx.x;

    __shared__ float4 smt[128][8];            // 16 KB column-reduce tree
    __shared__ float  s_a[CDIM], s_b[CDIM];   // 8 KB reduce trees
    __shared__ float  w_s[ROWS_PER];
    __shared__ float  sh_gate, sh_gamma, sh_invSr, sh_invSw;

    const int r0 = b * ROWS_PER;
    int nrows = NDIM - r0;
    if (nrows > ROWS_PER) nrows = ROWS_PER;
    if (nrows < 0) nrows = 0;

    // ===== Phase 0: prefetch this block's first 16 GEMV rows into L2 ======
    // 16 rows x 128 lines of 128B = 2048 lines; 2 per thread. DRAM absorbs
    // these during phase 1's idle bandwidth; phase 3 then hits L2 for them.
    {
        int pfrows = (nrows < 16) ? nrows : 16;
        const char* basep = (const char*)(mem + (size_t)r0 * MDIM);
#pragma unroll
        for (int j = 0; j < 2; j++) {
            int line = tid + j * 1024;          // 0..2047
            if (line < pfrows * 128) {
                const char* p = basep + (size_t)line * 128;
                asm volatile("prefetch.global.L2 [%0];" :: "l"(p));
            }
        }
    }

    // ============ Phase 1: GRU dot products, balanced schedule =============
    // 6144 ih half-rows (cost 5) + 6144 hh half-rows (cost 4) over 4736 warps:
    //   wg <  1920          : ih[2wg], ih[2wg+1]              (cost 10)
    //   1920 <= wg < 4224   : ih[3840+u], hh[2u], hh[2u+1]    (cost 13)
    //   4224 <= wg < 4736   : hh[4608+3v .. +2]               (cost 12)
    {
        const int lane = tid & 31;
        const int wg   = b * 32 + (tid >> 5);
        const float4* W_ih4 = (const float4*)W_ih;
        const float4* W_hh4 = (const float4*)W_hh;
        const float4* a4 = (const float4*)action;   // 64 groups
        const float4* x4 = (const float4*)hid;      // 256 groups
        const float4* h4 = (const float4*)hprev;    // 256 groups

        if (wg < 1920) {
            do_ih_piece(2 * wg,     lane, W_ih4, a4, x4);
            do_ih_piece(2 * wg + 1, lane, W_ih4, a4, x4);
        } else if (wg < 4224) {
            int u = wg - 1920;
            do_ih_piece(3840 + u,   lane, W_ih4, a4, x4);
            do_hh_piece(2 * u,      lane, W_hh4, h4);
            do_hh_piece(2 * u + 1,  lane, W_hh4, h4);
        } else {
            int v = wg - 4224;
            do_hh_piece(4608 + 3 * v,     lane, W_hh4, h4);
            do_hh_piece(4608 + 3 * v + 1, lane, W_hh4, h4);
            do_hh_piece(4608 + 3 * v + 2, lane, W_hh4, h4);
        }
    }
    grid_sync(&g_bar1);

    // == Phase 2: every block computes all h + gate/gamma (bit-identical) ===
    {
        int c = tid;   // 1024 channels, one per thread
        float d0 = g_dots_h[2 * c]                  + g_dots_h[2 * c + 1];
        float d1 = g_dots_h[2 * (CDIM + c)]         + g_dots_h[2 * (CDIM + c) + 1];
        float d2 = g_dots_h[2 * (2 * CDIM + c)]     + g_dots_h[2 * (2 * CDIM + c) + 1];
        float d3 = g_dots_h[2 * (3 * CDIM + c)]     + g_dots_h[2 * (3 * CDIM + c) + 1];
        float d4 = g_dots_h[2 * (4 * CDIM + c)]     + g_dots_h[2 * (4 * CDIM + c) + 1];
        float d5 = g_dots_h[2 * (5 * CDIM + c)]     + g_dots_h[2 * (5 * CDIM + c) + 1];
        float hp = hprev[c];
        float r = 1.f / (1.f + expf(-(d0 + b_ih[c] + d3 + b_hh[c])));
        float z = 1.f / (1.f + expf(-(d1 + b_ih[CDIM + c] + d4 + b_hh[CDIM + c])));
        float n = tanhf(d2 + b_ih[2 * CDIM + c] + r * (d5 + b_hh[2 * CDIM + c]));
        float h = (1.f - z) * n + z * hp;
        if (b == 0) out[MDIM + 2 * NDIM + c] = h;   // new_controller_hidden

        s_a[tid] = W_gate[c] * h;
        s_b[tid] = W_gamma[c] * h;
        __syncthreads();
        for (int off = 512; off > 0; off >>= 1) {
            if (tid < off) { s_a[tid] += s_a[tid + off]; s_b[tid] += s_b[tid + off]; }
            __syncthreads();
        }
        if (tid == 0) {
            sh_gate = 1.f / (1.f + expf(-(s_a[0] + b_gate[0])));
            float x = s_b[0] + b_gamma[0];
            sh_gamma = (x > 20.f) ? x : log1pf(expf(x));   // softplus
        }
        __syncthreads();
    }

    // ======== Phase 3: pow weights + streaming GEMV over own rows ==========
    {
        float gate = sh_gate, gamma = sh_gamma;
        if (tid < nrows) {
            int r = r0 + tid;
            float vr = gate + (1.f - gate) * prev_r[r];
            float vw = gate + (1.f - gate) * prev_w[r];
            float pr = powf(vr, gamma);
            float pw = powf(vw, gamma);
            g_pr[r] = pr; g_pw[r] = pw;
            w_s[tid] = pr;              // unnormalized weights drive the gemv
            s_a[tid] = pr; s_b[tid] = pw;
        }
        __syncthreads();
        if (tid == 0) {
            float sa = 0.f, sb = 0.f;
            for (int j = 0; j < nrows; j++) { sa += s_a[j]; sb += s_b[j]; }
            g_spr[b] = sa; g_spw[b] = sb;
        }

        if (nrows == ROWS_PER) {        // all full blocks (b < 146)
            const float4* m4 = (const float4*)mem + (size_t)r0 * (MDIM / 4) + tid;
            float4 acc0 = make_float4(0.f, 0.f, 0.f, 0.f);
            float4 acc1 = make_float4(0.f, 0.f, 0.f, 0.f);
#pragma unroll 1
            for (int i = 0; i < ROWS_PER; i += 8) {
                float4 v[8];
                float  w[8];
#pragma unroll
                for (int j = 0; j < 8; j++) {
                    v[j] = __ldcs(m4 + (size_t)(i + j) * (MDIM / 4));
                    w[j] = w_s[i + j];
                }
#pragma unroll
                for (int j = 0; j < 8; j += 2) {
                    acc0.x += w[j] * v[j].x; acc0.y += w[j] * v[j].y;
                    acc0.z += w[j] * v[j].z; acc0.w += w[j] * v[j].w;
                    acc1.x += w[j+1] * v[j+1].x; acc1.y += w[j+1] * v[j+1].y;
                    acc1.z += w[j+1] * v[j+1].z; acc1.w += w[j+1] * v[j+1].w;
                }
            }
            acc0.x += acc1.x; acc0.y += acc1.y; acc0.z += acc1.z; acc0.w += acc1.w;
            ((float4*)g_partial)[(size_t)b * (MDIM / 4) + tid] = acc0;
        } else {                         // tail blocks (b=146: 16 rows, b=147: 0)
            const float4* m4 = (const float4*)mem + (size_t)r0 * (MDIM / 4) + tid;
            float4 acc0 = make_float4(0.f, 0.f, 0.f, 0.f);
            for (int i = 0; i < nrows; i++) {
                float w0 = w_s[i];
                float4 v0 = __ldcs(m4 + (size_t)i * (MDIM / 4));
                acc0.x += w0 * v0.x; acc0.y += w0 * v0.y;
                acc0.z += w0 * v0.z; acc0.w += w0 * v0.w;
            }
            ((float4*)g_partial)[(size_t)b * (MDIM / 4) + tid] = acc0;
        }
    }
    grid_sync(&g_bar2);

    // ================= Phase 4: normalize + column reduce ==================
    {
        if (tid < 256) {
            s_a[tid] = (tid < NBLK) ? g_spr[tid] : 0.f;
            s_b[tid] = (tid < NBLK) ? g_spw[tid] : 0.f;
        }
        __syncthreads();
        for (int off = 128; off > 0; off >>= 1) {
            if (tid < off && tid < 256) { s_a[tid] += s_a[tid + off]; s_b[tid] += s_b[tid + off]; }
            __syncthreads();
        }
        if (tid == 0) { sh_invSr = 1.f / s_a[0]; sh_invSw = 1.f / s_b[0]; }
        __syncthreads();
        float invSr = sh_invSr, invSw = sh_invSw;

        if (tid < nrows) {
            int r = r0 + tid;
            out[MDIM + r]        = g_pr[r] * invSr;  // read_weight
            out[MDIM + NDIM + r] = g_pw[r] * invSw;  // write_weight
        }

        // read_vector: blocks 0..127 each own 8 float4 column groups
        if (b < 128) {
            int cl    = tid & 7;
            int slice = tid >> 3;                    // 0..127
            int g4    = b * 8 + cl;
            const float4* p4 = (const float4*)g_partial + g4;
            float4 acc = make_float4(0.f, 0.f, 0.f, 0.f);
            for (int r = slice; r < NBLK; r += 128) {
                float4 v = p4[(size_t)r * (MDIM / 4)];
                acc.x += v.x; acc.y += v.y; acc.z += v.z; acc.w += v.w;
            }
            smt[slice][cl] = acc;
            __syncthreads();
            for (int off = 64; off > 0; off >>= 1) {
                if (slice < off) {
                    float4 a = smt[slice][cl];
                    float4 c = smt[slice + off][cl];
                    a.x += c.x; a.y += c.y; a.z += c.z; a.w += c.w;
                    smt[slice][cl] = a;
                }
                __syncthreads();
            }
            if (slice == 0) {
                float4 a = smt[0][cl];
                a.x *= invSr; a.y *= invSr; a.z *= invSr; a.w *= invSr;
                ((float4*)out)[g4] = a;              // read_vector
            }
        }
    }
}

extern "C" void kernel_launch(void* const* d_in, const int* in_sizes, int n_in,
                              void* d_out, int out_size)
{
    const float* action  = (const float*)d_in[0];   // (1,256)
    const float* hid     = (const float*)d_in[1];   // (1,1,1024)
    const float* prev_r  = (const float*)d_in[2];   // (8192,1)
    const float* prev_w  = (const float*)d_in[3];   // (8192,1)
    const float* hprev   = (const float*)d_in[4];   // (1,1,1024)
    const float* memory  = (const float*)d_in[5];   // (8192,4096)
    const float* W_ih    = (const float*)d_in[6];   // (3072,1280)
    const float* W_hh    = (const float*)d_in[7];   // (3072,1024)
    const float* b_ih    = (const float*)d_in[8];
    const float* b_hh    = (const float*)d_in[9];
    // d_in[10..19]: dead code (cosine-sim == 1, circ-conv scalar cancels in
    // sharpen, memory write discarded)
    const float* W_gamma = (const float*)d_in[20];
    const float* b_gamma = (const float*)d_in[21];
    const float* W_gate  = (const float*)d_in[22];
    const float* b_gate  = (const float*)d_in[23];

    float* out = (float*)d_out;
    // Layout: [0:4096) read_vector | [4096:12288) read_weight |
    //         [12288:20480) write_weight | [20480:21504) new_controller_hidden

    fused_kernel<<<NBLK, 1024>>>(action, hid, prev_r, prev_w, hprev, memory,
                                 W_ih, W_hh, b_ih, b_hh,
                                 W_gamma, b_gamma, W_gate, b_gate, out);
}